// round 1
// baseline (speedup 1.0000x reference)
#include <cuda_runtime.h>
#include <cuda_bf16.h>
#include <mma.h>
#include <cstdint>
#include <cstddef>

using namespace nvcuda;

// Problem constants
#define BB 16384   // batch
#define NF 512     // features
#define NU 256     // used features
#define NL 1024    // leaves / decision nodes slots
#define NC 100     // classes
#define NCP 128    // classes padded for GEMM2

// -------- device scratch (static; no allocations anywhere) --------
__device__ int            g_idx[NU];
__device__ __nv_bfloat16  g_xb[(size_t)BB * NU];    // gathered features, bf16
__device__ __nv_bfloat16  g_Wb[(size_t)NU * NL];    // W in bf16, [k][n]
__device__ __nv_bfloat16  g_probs[(size_t)NL * NCP];// softmax(pi), padded cols 100..127 = 0
__device__ __nv_bfloat16  g_d[(size_t)BB * NL];     // sigmoid decisions
__device__ __nv_bfloat16  g_mu[(size_t)BB * NL];    // leaf routing probs

// -------- prep kernels --------
__global__ void k_idx(const float* __restrict__ mask) {
    int j = threadIdx.x;
    int found = 0;
    for (int f = 0; f < NF; f++) {
        if (mask[(size_t)j * NF + f] > 0.5f) { found = f; break; }
    }
    g_idx[j] = found;
}

__global__ void k_gather(const float* __restrict__ feat) {
    __shared__ int sidx[NU];
    int tid = threadIdx.x;
    sidx[tid] = g_idx[tid];
    __syncthreads();
    int row = blockIdx.x;
    g_xb[(size_t)row * NU + tid] = __float2bfloat16(feat[(size_t)row * NF + sidx[tid]]);
}

__global__ void k_wconv(const float* __restrict__ W) {
    for (int i = blockIdx.x * blockDim.x + threadIdx.x; i < NU * NL; i += gridDim.x * blockDim.x)
        g_Wb[i] = __float2bfloat16(W[i]);
}

__global__ void k_softmax(const float* __restrict__ pi) {
    __shared__ float sv[NCP];
    __shared__ float smax, ssum;
    int l = blockIdx.x, c = threadIdx.x;
    float v = (c < NC) ? pi[(size_t)l * NC + c] : -1e30f;
    sv[c] = v;
    __syncthreads();
    if (c == 0) {
        float m = sv[0];
        for (int i = 1; i < NC; i++) m = fmaxf(m, sv[i]);
        smax = m;
    }
    __syncthreads();
    float e = (c < NC) ? expf(v - smax) : 0.f;
    sv[c] = e;
    __syncthreads();
    if (c == 0) {
        float s = 0.f;
        for (int i = 0; i < NC; i++) s += sv[i];
        ssum = s;
    }
    __syncthreads();
    g_probs[(size_t)l * NCP + c] = __float2bfloat16(e / ssum);
}

// -------- GEMM1: d = sigmoid(xb @ Wb + b), bf16 wmma, tiles 128x128, BK=64 --------
__global__ __launch_bounds__(256) void k_gemm1(const float* __restrict__ bias) {
    __shared__ __align__(16) unsigned char smem[40960];
    __nv_bfloat16* As = reinterpret_cast<__nv_bfloat16*>(smem);            // [128][80]
    __nv_bfloat16* Bs = reinterpret_cast<__nv_bfloat16*>(smem + 20480);    // [64][144]
    float*         Cs = reinterpret_cast<float*>(smem);                    // [64][132] (reuse)

    int tid = threadIdx.x, wid = tid >> 5;
    int wm = wid & 3, wn = wid >> 2;           // 4x2 warp grid, warp tile 32x64
    int row0 = blockIdx.y * 128, n0 = blockIdx.x * 128;

    wmma::fragment<wmma::accumulator, 16, 16, 16, float> acc[2][4];
#pragma unroll
    for (int i = 0; i < 2; i++)
#pragma unroll
        for (int j = 0; j < 4; j++) wmma::fill_fragment(acc[i][j], 0.f);

    for (int ko = 0; ko < NU; ko += 64) {
        __syncthreads();
#pragma unroll
        for (int s = tid; s < 1024; s += 256) {   // A: 128 rows x 8 uint4
            int r = s >> 3, c = (s & 7) * 8;
            *reinterpret_cast<uint4*>(As + r * 80 + c) =
                *reinterpret_cast<const uint4*>(g_xb + (size_t)(row0 + r) * NU + ko + c);
        }
#pragma unroll
        for (int s = tid; s < 1024; s += 256) {   // B: 64 rows x 16 uint4
            int r = s >> 4, c = (s & 15) * 8;
            *reinterpret_cast<uint4*>(Bs + r * 144 + c) =
                *reinterpret_cast<const uint4*>(g_Wb + (size_t)(ko + r) * NL + n0 + c);
        }
        __syncthreads();
#pragma unroll
        for (int kk = 0; kk < 4; kk++) {
            wmma::fragment<wmma::matrix_a, 16, 16, 16, __nv_bfloat16, wmma::row_major> af[2];
            wmma::fragment<wmma::matrix_b, 16, 16, 16, __nv_bfloat16, wmma::row_major> bfr[4];
#pragma unroll
            for (int i = 0; i < 2; i++)
                wmma::load_matrix_sync(af[i], As + (wm * 32 + i * 16) * 80 + kk * 16, 80);
#pragma unroll
            for (int j = 0; j < 4; j++)
                wmma::load_matrix_sync(bfr[j], Bs + (kk * 16) * 144 + wn * 64 + j * 16, 144);
#pragma unroll
            for (int i = 0; i < 2; i++)
#pragma unroll
                for (int j = 0; j < 4; j++)
                    wmma::mma_sync(acc[i][j], af[i], bfr[j], acc[i][j]);
        }
    }
    __syncthreads();

    // epilogue in two 64-row halves (SMEM reuse), bias + sigmoid, store bf16
    for (int h = 0; h < 2; h++) {
        if ((wm >> 1) == h) {
#pragma unroll
            for (int i = 0; i < 2; i++)
#pragma unroll
                for (int j = 0; j < 4; j++)
                    wmma::store_matrix_sync(Cs + ((wm & 1) * 32 + i * 16) * 132 + wn * 64 + j * 16,
                                            acc[i][j], 132, wmma::mem_row_major);
        }
        __syncthreads();
#pragma unroll
        for (int s = tid; s < 64 * 128; s += 256) {
            int r = s >> 7, c = s & 127;
            float z = Cs[r * 132 + c] + bias[n0 + c];
            float dv = 1.f / (1.f + __expf(-z));
            g_d[(size_t)(row0 + h * 64 + r) * NL + n0 + c] = __float2bfloat16(dv);
        }
        __syncthreads();
    }
}

// -------- tree product: mu from d --------
// block = 16 rows, 256 threads; thread (r = tid>>4, t = tid&15) handles leaves [64t, 64t+64)
__global__ __launch_bounds__(256) void k_mu() {
    __shared__ __align__(16) __nv_bfloat16 ds[16 * 1032];   // padded rows, 33 KB
    int tid = threadIdx.x;
    int row0 = blockIdx.x * 16;
#pragma unroll
    for (int s = tid; s < 2048; s += 256) {     // 16 rows x 128 uint4
        int r = s >> 7, c = (s & 127) * 8;
        *reinterpret_cast<uint4*>(ds + r * 1032 + c) =
            *reinterpret_cast<const uint4*>(g_d + (size_t)(row0 + r) * NL + c);
    }
    __syncthreads();

    int r = tid >> 4, t = tid & 15;
    const __nv_bfloat16* dr = ds + r * 1032;

    // prefix over levels 0..3 (constant per 64-leaf chunk)
    float P = 1.f;
#pragma unroll
    for (int lev = 0; lev < 4; lev++) {
        int node = (1 << lev) + (t >> (4 - lev));
        int bit  = (t >> (3 - lev)) & 1;
        float dv = __bfloat162float(dr[node]);
        P *= bit ? (1.f - dv) : dv;
    }

    __nv_bfloat16* dst = g_mu + (size_t)(row0 + r) * NL + t * 64;
#pragma unroll
    for (int g = 0; g < 8; g++) {               // groups of 8 leaves
        int q = 8 * t + g;
        float Pg = P, dv;
        dv = __bfloat162float(dr[16 + t]);               Pg *= ((g >> 2) & 1) ? (1.f - dv) : dv; // lev 4
        dv = __bfloat162float(dr[32 + 2 * t + (g >> 2)]); Pg *= ((g >> 1) & 1) ? (1.f - dv) : dv; // lev 5
        dv = __bfloat162float(dr[64 + 4 * t + (g >> 1)]); Pg *= (g & 1) ? (1.f - dv) : dv;        // lev 6
        float d7  = __bfloat162float(dr[128 + q]);
        float d8a = __bfloat162float(dr[256 + 2 * q]);
        float d8b = __bfloat162float(dr[256 + 2 * q + 1]);
        float d90 = __bfloat162float(dr[512 + 4 * q]);
        float d91 = __bfloat162float(dr[512 + 4 * q + 1]);
        float d92 = __bfloat162float(dr[512 + 4 * q + 2]);
        float d93 = __bfloat162float(dr[512 + 4 * q + 3]);
        float pa = Pg * d7;            // leaves j=0..3
        float pb = Pg * (1.f - d7);    // leaves j=4..7
        float m0 = pa * d8a * d90;
        float m1 = pa * d8a * (1.f - d90);
        float m2 = pa * (1.f - d8a) * d91;
        float m3 = pa * (1.f - d8a) * (1.f - d91);
        float m4 = pb * d8b * d92;
        float m5 = pb * d8b * (1.f - d92);
        float m6 = pb * (1.f - d8b) * d93;
        float m7 = pb * (1.f - d8b) * (1.f - d93);
        __nv_bfloat162 p0 = __floats2bfloat162_rn(m0, m1);
        __nv_bfloat162 p1 = __floats2bfloat162_rn(m2, m3);
        __nv_bfloat162 p2 = __floats2bfloat162_rn(m4, m5);
        __nv_bfloat162 p3 = __floats2bfloat162_rn(m6, m7);
        uint4 u;
        u.x = *reinterpret_cast<unsigned*>(&p0);
        u.y = *reinterpret_cast<unsigned*>(&p1);
        u.z = *reinterpret_cast<unsigned*>(&p2);
        u.w = *reinterpret_cast<unsigned*>(&p3);
        *reinterpret_cast<uint4*>(dst + 8 * g) = u;
    }
}

// -------- GEMM2: out = mu @ probs, bf16 wmma, tiles 128x128, BK=64, K=1024 --------
__global__ __launch_bounds__(256) void k_gemm2(float* __restrict__ out) {
    __shared__ __align__(16) unsigned char smem[40960];
    __nv_bfloat16* As = reinterpret_cast<__nv_bfloat16*>(smem);            // [128][80]
    __nv_bfloat16* Bs = reinterpret_cast<__nv_bfloat16*>(smem + 20480);    // [64][144]
    float*         Cs = reinterpret_cast<float*>(smem);                    // [64][132]

    int tid = threadIdx.x, wid = tid >> 5;
    int wm = wid & 3, wn = wid >> 2;
    int row0 = blockIdx.x * 128;

    wmma::fragment<wmma::accumulator, 16, 16, 16, float> acc[2][4];
#pragma unroll
    for (int i = 0; i < 2; i++)
#pragma unroll
        for (int j = 0; j < 4; j++) wmma::fill_fragment(acc[i][j], 0.f);

    for (int ko = 0; ko < NL; ko += 64) {
        __syncthreads();
#pragma unroll
        for (int s = tid; s < 1024; s += 256) {
            int r = s >> 3, c = (s & 7) * 8;
            *reinterpret_cast<uint4*>(As + r * 80 + c) =
                *reinterpret_cast<const uint4*>(g_mu + (size_t)(row0 + r) * NL + ko + c);
        }
#pragma unroll
        for (int s = tid; s < 1024; s += 256) {
            int r = s >> 4, c = (s & 15) * 8;
            *reinterpret_cast<uint4*>(Bs + r * 144 + c) =
                *reinterpret_cast<const uint4*>(g_probs + (size_t)(ko + r) * NCP + c);
        }
        __syncthreads();
#pragma unroll
        for (int kk = 0; kk < 4; kk++) {
            wmma::fragment<wmma::matrix_a, 16, 16, 16, __nv_bfloat16, wmma::row_major> af[2];
            wmma::fragment<wmma::matrix_b, 16, 16, 16, __nv_bfloat16, wmma::row_major> bfr[4];
#pragma unroll
            for (int i = 0; i < 2; i++)
                wmma::load_matrix_sync(af[i], As + (wm * 32 + i * 16) * 80 + kk * 16, 80);
#pragma unroll
            for (int j = 0; j < 4; j++)
                wmma::load_matrix_sync(bfr[j], Bs + (kk * 16) * 144 + wn * 64 + j * 16, 144);
#pragma unroll
            for (int i = 0; i < 2; i++)
#pragma unroll
                for (int j = 0; j < 4; j++)
                    wmma::mma_sync(acc[i][j], af[i], bfr[j], acc[i][j]);
        }
    }
    __syncthreads();

    for (int h = 0; h < 2; h++) {
        if ((wm >> 1) == h) {
#pragma unroll
            for (int i = 0; i < 2; i++)
#pragma unroll
                for (int j = 0; j < 4; j++)
                    wmma::store_matrix_sync(Cs + ((wm & 1) * 32 + i * 16) * 132 + wn * 64 + j * 16,
                                            acc[i][j], 132, wmma::mem_row_major);
        }
        __syncthreads();
#pragma unroll
        for (int s = tid; s < 64 * 128; s += 256) {
            int r = s >> 7, c = s & 127;
            if (c < NC)
                out[(size_t)(row0 + h * 64 + r) * NC + c] = Cs[r * 132 + c];
        }
        __syncthreads();
    }
}

// -------- launch --------
extern "C" void kernel_launch(void* const* d_in, const int* in_sizes, int n_in,
                              void* d_out, int out_size) {
    const float* feat = nullptr;
    const float* mask = nullptr;
    const float* W    = nullptr;
    const float* bias = nullptr;
    const float* pi   = nullptr;
    for (int i = 0; i < n_in; i++) {
        switch (in_sizes[i]) {
            case BB * NF: feat = (const float*)d_in[i]; break;   // 8388608
            case NU * NF: mask = (const float*)d_in[i]; break;   // 131072
            case NU * NL: W    = (const float*)d_in[i]; break;   // 262144
            case NL:      bias = (const float*)d_in[i]; break;   // 1024
            case NL * NC: pi   = (const float*)d_in[i]; break;   // 102400
            default: break;
        }
    }
    // positional fallback (metadata order: features, mask, W, b, pi)
    if (!feat && n_in > 0) feat = (const float*)d_in[0];
    if (!mask && n_in > 1) mask = (const float*)d_in[1];
    if (!W    && n_in > 2) W    = (const float*)d_in[2];
    if (!bias && n_in > 3) bias = (const float*)d_in[3];
    if (!pi   && n_in > 4) pi   = (const float*)d_in[4];

    k_idx<<<1, NU>>>(mask);
    k_gather<<<BB, NU>>>(feat);
    k_wconv<<<256, 256>>>(W);
    k_softmax<<<NL, NCP>>>(pi);
    k_gemm1<<<dim3(NL / 128, BB / 128), 256>>>(bias);
    k_mu<<<BB / 16, 256>>>();
    k_gemm2<<<BB / 128, 256>>>((float*)d_out);
    (void)out_size;
}

// round 3
// speedup vs baseline: 1.4767x; 1.4767x over previous
#include <cuda_runtime.h>
#include <cuda_bf16.h>
#include <mma.h>
#include <cstdint>
#include <cstddef>

using namespace nvcuda;

#define BB 16384   // batch
#define NF 512     // features
#define NU 256     // used features
#define NL 1024    // leaves / decision node slots
#define NC 100     // classes
#define NCP 128    // classes padded

// -------- device scratch (static; no allocations anywhere) --------
__device__ int            g_idx[NU];
__device__ __nv_bfloat16  g_xb[(size_t)BB * NU];
__device__ __nv_bfloat16  g_Wb[(size_t)NU * NL];
__device__ __nv_bfloat16  g_probs[(size_t)NL * NCP];
__device__ __nv_bfloat16  g_d[(size_t)BB * NL];
__device__ __nv_bfloat16  g_mu[(size_t)BB * NL];

// -------- cp.async helpers --------
__device__ __forceinline__ void cpa16(void* smem, const void* gmem) {
    uint32_t s = (uint32_t)__cvta_generic_to_shared(smem);
    asm volatile("cp.async.cg.shared.global [%0], [%1], 16;\n" :: "r"(s), "l"(gmem));
}
__device__ __forceinline__ void cpa_commit() { asm volatile("cp.async.commit_group;\n" ::: "memory"); }
template<int N> __device__ __forceinline__ void cpa_wait() { asm volatile("cp.async.wait_group %0;\n" :: "n"(N) : "memory"); }

// -------- prep: one block per used-feature, find its one-hot column --------
__global__ void k_idx(const float* __restrict__ mask) {
    int j = blockIdx.x;                 // 256 blocks, 128 threads
    int t = threadIdx.x;
    float4 v = reinterpret_cast<const float4*>(mask + (size_t)j * NF)[t];
    int f = -1;
    if      (v.x > 0.5f) f = 4 * t;
    else if (v.y > 0.5f) f = 4 * t + 1;
    else if (v.z > 0.5f) f = 4 * t + 2;
    else if (v.w > 0.5f) f = 4 * t + 3;
    if (f >= 0) g_idx[j] = f;
}

// -------- coalesced gather: 4 rows/block via SMEM staging --------
__global__ __launch_bounds__(256) void k_gather(const float* __restrict__ feat) {
    __shared__ float rows[4][NF];
    __shared__ int sidx[NU];
    int t = threadIdx.x;
    sidx[t] = g_idx[t];
    int row0 = blockIdx.x * 4;
    const float4* src = reinterpret_cast<const float4*>(feat + (size_t)row0 * NF);
    float4* dst4 = reinterpret_cast<float4*>(&rows[0][0]);
    dst4[t] = src[t];
    dst4[t + 256] = src[t + 256];
    __syncthreads();
#pragma unroll
    for (int r = 0; r < 4; r++)
        g_xb[(size_t)(row0 + r) * NU + t] = __float2bfloat16(rows[r][sidx[t]]);
}

// -------- W f32 -> bf16, vectorized --------
__global__ void k_wconv(const float* __restrict__ W) {
    int i = blockIdx.x * blockDim.x + threadIdx.x;   // 65536 threads, 4 elems each
    float4 v = reinterpret_cast<const float4*>(W)[i];
    __nv_bfloat162 p0 = __floats2bfloat162_rn(v.x, v.y);
    __nv_bfloat162 p1 = __floats2bfloat162_rn(v.z, v.w);
    uint2 u;
    u.x = *reinterpret_cast<unsigned*>(&p0);
    u.y = *reinterpret_cast<unsigned*>(&p1);
    reinterpret_cast<uint2*>(g_Wb)[i] = u;
}

// -------- softmax(pi): one warp per leaf row --------
__global__ __launch_bounds__(256) void k_softmax(const float* __restrict__ pi) {
    int w = blockIdx.x * 8 + (threadIdx.x >> 5);   // 128 blocks x 8 warps = 1024 rows
    int lane = threadIdx.x & 31;
    const float* row = pi + (size_t)w * NC;        // 400B rows -> 16B aligned
    float4 v;
    if (lane < 25) v = reinterpret_cast<const float4*>(row)[lane];
    else v = make_float4(-1e30f, -1e30f, -1e30f, -1e30f);
    float m = fmaxf(fmaxf(v.x, v.y), fmaxf(v.z, v.w));
#pragma unroll
    for (int o = 16; o > 0; o >>= 1) m = fmaxf(m, __shfl_xor_sync(0xffffffffu, m, o));
    float e0 = (lane < 25) ? expf(v.x - m) : 0.f;
    float e1 = (lane < 25) ? expf(v.y - m) : 0.f;
    float e2 = (lane < 25) ? expf(v.z - m) : 0.f;
    float e3 = (lane < 25) ? expf(v.w - m) : 0.f;
    float s = e0 + e1 + e2 + e3;
#pragma unroll
    for (int o = 16; o > 0; o >>= 1) s += __shfl_xor_sync(0xffffffffu, s, o);
    float inv = 1.f / s;
    __nv_bfloat162 p0 = __floats2bfloat162_rn(e0 * inv, e1 * inv);
    __nv_bfloat162 p1 = __floats2bfloat162_rn(e2 * inv, e3 * inv);
    uint2 u;
    u.x = *reinterpret_cast<unsigned*>(&p0);
    u.y = *reinterpret_cast<unsigned*>(&p1);
    reinterpret_cast<uint2*>(g_probs + (size_t)w * NCP)[lane] = u;  // lanes 25-31 write the zero pad
}

// -------- GEMM1: d = sigmoid(xb @ Wb + b)  [16384x1024x256]
// 128x128 tile, BK=32, 2-stage cp.async. 8 warps = 4(m) x 2(n), warp tile 32x64.
#define G1_AS 40    // A smem stride (bf16 elems)
#define G1_BS 136   // B smem stride
__global__ __launch_bounds__(256) void k_gemm1(const float* __restrict__ bias) {
    __shared__ __align__(16) unsigned char smem[38912];
    __nv_bfloat16* As = reinterpret_cast<__nv_bfloat16*>(smem);                  // 2 x 128x40
    __nv_bfloat16* Bs = reinterpret_cast<__nv_bfloat16*>(smem + 2 * 128 * G1_AS * 2); // 2 x 32x136
    float*         Cs = reinterpret_cast<float*>(smem);                          // 64x132 (reuse)

    int tid = threadIdx.x, wid = tid >> 5;
    int wm = wid & 3, wn = wid >> 2;
    int row0 = blockIdx.y * 128, n0 = blockIdx.x * 128;

    wmma::fragment<wmma::accumulator, 16, 16, 16, float> acc[2][4];
#pragma unroll
    for (int i = 0; i < 2; i++)
#pragma unroll
        for (int j = 0; j < 4; j++) wmma::fill_fragment(acc[i][j], 0.f);

    auto load_stage = [&](int st, int ko) {
        __nv_bfloat16* a = As + st * 128 * G1_AS;
        __nv_bfloat16* b = Bs + st * 32 * G1_BS;
        // A: 128 rows x 32 cols = 512 uint4, 2/thread
#pragma unroll
        for (int s = tid; s < 512; s += 256) {
            int r = s >> 2, c = (s & 3) * 8;
            cpa16(a + r * G1_AS + c, g_xb + (size_t)(row0 + r) * NU + ko + c);
        }
        // B: 32 rows x 128 cols = 512 uint4, 2/thread
#pragma unroll
        for (int s = tid; s < 512; s += 256) {
            int r = s >> 4, c = (s & 15) * 8;
            cpa16(b + r * G1_BS + c, g_Wb + (size_t)(ko + r) * NL + n0 + c);
        }
        cpa_commit();
    };

    load_stage(0, 0);
    const int NCH = NU / 32;   // 8
    for (int ch = 0; ch < NCH; ch++) {
        if (ch + 1 < NCH) { load_stage((ch + 1) & 1, (ch + 1) * 32); cpa_wait<1>(); }
        else              { cpa_wait<0>(); }
        __syncthreads();
        const __nv_bfloat16* a = As + (ch & 1) * 128 * G1_AS;
        const __nv_bfloat16* b = Bs + (ch & 1) * 32 * G1_BS;
#pragma unroll
        for (int kk = 0; kk < 2; kk++) {
            wmma::fragment<wmma::matrix_a, 16, 16, 16, __nv_bfloat16, wmma::row_major> af[2];
            wmma::fragment<wmma::matrix_b, 16, 16, 16, __nv_bfloat16, wmma::row_major> bf[4];
#pragma unroll
            for (int i = 0; i < 2; i++)
                wmma::load_matrix_sync(af[i], a + (wm * 32 + i * 16) * G1_AS + kk * 16, G1_AS);
#pragma unroll
            for (int j = 0; j < 4; j++)
                wmma::load_matrix_sync(bf[j], b + (kk * 16) * G1_BS + wn * 64 + j * 16, G1_BS);
#pragma unroll
            for (int i = 0; i < 2; i++)
#pragma unroll
                for (int j = 0; j < 4; j++)
                    wmma::mma_sync(acc[i][j], af[i], bf[j], acc[i][j]);
        }
        __syncthreads();
    }

    // epilogue: two 64-row halves through SMEM, bias + sigmoid, bf16 store
    for (int h = 0; h < 2; h++) {
        if ((wm >> 1) == h) {
#pragma unroll
            for (int i = 0; i < 2; i++)
#pragma unroll
                for (int j = 0; j < 4; j++)
                    wmma::store_matrix_sync(Cs + ((wm & 1) * 32 + i * 16) * 132 + wn * 64 + j * 16,
                                            acc[i][j], 132, wmma::mem_row_major);
        }
        __syncthreads();
#pragma unroll
        for (int s = tid; s < 64 * 128; s += 256) {
            int r = s >> 7, c = s & 127;
            float z = Cs[r * 132 + c] + bias[n0 + c];
            float dv = 1.f / (1.f + __expf(-z));
            g_d[(size_t)(row0 + h * 64 + r) * NL + n0 + c] = __float2bfloat16(dv);
        }
        __syncthreads();
    }
}

// -------- tree product: mu from d (16 rows/block) --------
__global__ __launch_bounds__(256) void k_mu() {
    __shared__ __align__(16) __nv_bfloat16 ds[16 * 1032];
    int tid = threadIdx.x;
    int row0 = blockIdx.x * 16;
#pragma unroll
    for (int s = tid; s < 2048; s += 256) {
        int r = s >> 7, c = (s & 127) * 8;
        *reinterpret_cast<uint4*>(ds + r * 1032 + c) =
            *reinterpret_cast<const uint4*>(g_d + (size_t)(row0 + r) * NL + c);
    }
    __syncthreads();

    int r = tid >> 4, t = tid & 15;
    const __nv_bfloat16* dr = ds + r * 1032;

    float P = 1.f;
#pragma unroll
    for (int lev = 0; lev < 4; lev++) {
        int node = (1 << lev) + (t >> (4 - lev));
        int bit  = (t >> (3 - lev)) & 1;
        float dv = __bfloat162float(dr[node]);
        P *= bit ? (1.f - dv) : dv;
    }

    __nv_bfloat16* dst = g_mu + (size_t)(row0 + r) * NL + t * 64;
#pragma unroll
    for (int g = 0; g < 8; g++) {
        int q = 8 * t + g;
        float Pg = P, dv;
        dv = __bfloat162float(dr[16 + t]);                Pg *= ((g >> 2) & 1) ? (1.f - dv) : dv;
        dv = __bfloat162float(dr[32 + 2 * t + (g >> 2)]); Pg *= ((g >> 1) & 1) ? (1.f - dv) : dv;
        dv = __bfloat162float(dr[64 + 4 * t + (g >> 1)]); Pg *= (g & 1) ? (1.f - dv) : dv;
        float d7  = __bfloat162float(dr[128 + q]);
        float d8a = __bfloat162float(dr[256 + 2 * q]);
        float d8b = __bfloat162float(dr[256 + 2 * q + 1]);
        float d90 = __bfloat162float(dr[512 + 4 * q]);
        float d91 = __bfloat162float(dr[512 + 4 * q + 1]);
        float d92 = __bfloat162float(dr[512 + 4 * q + 2]);
        float d93 = __bfloat162float(dr[512 + 4 * q + 3]);
        float pa = Pg * d7;
        float pb = Pg * (1.f - d7);
        float m0 = pa * d8a * d90;
        float m1 = pa * d8a * (1.f - d90);
        float m2 = pa * (1.f - d8a) * d91;
        float m3 = pa * (1.f - d8a) * (1.f - d91);
        float m4 = pb * d8b * d92;
        float m5 = pb * d8b * (1.f - d92);
        float m6 = pb * (1.f - d8b) * d93;
        float m7 = pb * (1.f - d8b) * (1.f - d93);
        __nv_bfloat162 p0 = __floats2bfloat162_rn(m0, m1);
        __nv_bfloat162 p1 = __floats2bfloat162_rn(m2, m3);
        __nv_bfloat162 p2 = __floats2bfloat162_rn(m4, m5);
        __nv_bfloat162 p3 = __floats2bfloat162_rn(m6, m7);
        uint4 u;
        u.x = *reinterpret_cast<unsigned*>(&p0);
        u.y = *reinterpret_cast<unsigned*>(&p1);
        u.z = *reinterpret_cast<unsigned*>(&p2);
        u.w = *reinterpret_cast<unsigned*>(&p3);
        *reinterpret_cast<uint4*>(dst + 8 * g) = u;
    }
}

// -------- GEMM2: out = mu @ probs  [16384x128x1024]
// 64x128 tile, BK=32, 2-stage cp.async. 8 warps = 2(m) x 4(n), warp tile 32x32.
#define G2_AS 40
#define G2_BS 136
__global__ __launch_bounds__(256) void k_gemm2(float* __restrict__ out) {
    __shared__ __align__(16) unsigned char smem[33792];
    __nv_bfloat16* As = reinterpret_cast<__nv_bfloat16*>(smem);                  // 2 x 64x40
    __nv_bfloat16* Bs = reinterpret_cast<__nv_bfloat16*>(smem + 2 * 64 * G2_AS * 2); // 2 x 32x136
    float*         Cs = reinterpret_cast<float*>(smem);                          // 64x132 (reuse)

    int tid = threadIdx.x, wid = tid >> 5;
    int wm = wid & 1, wn = wid >> 1;
    int row0 = blockIdx.x * 64;

    wmma::fragment<wmma::accumulator, 16, 16, 16, float> acc[2][2];
#pragma unroll
    for (int i = 0; i < 2; i++)
#pragma unroll
        for (int j = 0; j < 2; j++) wmma::fill_fragment(acc[i][j], 0.f);

    auto load_stage = [&](int st, int ko) {
        __nv_bfloat16* a = As + st * 64 * G2_AS;
        __nv_bfloat16* b = Bs + st * 32 * G2_BS;
        // A: 64 x 32 = 256 uint4, exactly 1/thread
        {
            int s = tid;
            int r = s >> 2, c = (s & 3) * 8;
            cpa16(a + r * G2_AS + c, g_mu + (size_t)(row0 + r) * NL + ko + c);
        }
        // B: 32 x 128 = 512 uint4, 2/thread
#pragma unroll
        for (int s = tid; s < 512; s += 256) {
            int r = s >> 4, c = (s & 15) * 8;
            cpa16(b + r * G2_BS + c, g_probs + (size_t)(ko + r) * NCP + c);
        }
        cpa_commit();
    };

    load_stage(0, 0);
    const int NCH = NL / 32;   // 32
    for (int ch = 0; ch < NCH; ch++) {
        if (ch + 1 < NCH) { load_stage((ch + 1) & 1, (ch + 1) * 32); cpa_wait<1>(); }
        else              { cpa_wait<0>(); }
        __syncthreads();
        const __nv_bfloat16* a = As + (ch & 1) * 64 * G2_AS;
        const __nv_bfloat16* b = Bs + (ch & 1) * 32 * G2_BS;
#pragma unroll
        for (int kk = 0; kk < 2; kk++) {
            wmma::fragment<wmma::matrix_a, 16, 16, 16, __nv_bfloat16, wmma::row_major> af[2];
            wmma::fragment<wmma::matrix_b, 16, 16, 16, __nv_bfloat16, wmma::row_major> bf[2];
#pragma unroll
            for (int i = 0; i < 2; i++)
                wmma::load_matrix_sync(af[i], a + (wm * 32 + i * 16) * G2_AS + kk * 16, G2_AS);
#pragma unroll
            for (int j = 0; j < 2; j++)
                wmma::load_matrix_sync(bf[j], b + (kk * 16) * G2_BS + wn * 32 + j * 16, G2_BS);
#pragma unroll
            for (int i = 0; i < 2; i++)
#pragma unroll
                for (int j = 0; j < 2; j++)
                    wmma::mma_sync(acc[i][j], af[i], bf[j], acc[i][j]);
        }
        __syncthreads();
    }

    // epilogue: 64x128 through SMEM, write cols < 100
#pragma unroll
    for (int i = 0; i < 2; i++)
#pragma unroll
        for (int j = 0; j < 2; j++)
            wmma::store_matrix_sync(Cs + (wm * 32 + i * 16) * 132 + wn * 32 + j * 16,
                                    acc[i][j], 132, wmma::mem_row_major);
    __syncthreads();
#pragma unroll
    for (int s = tid; s < 64 * 128; s += 256) {
        int r = s >> 7, c = s & 127;
        if (c < NC)
            out[(size_t)(row0 + r) * NC + c] = Cs[r * 132 + c];
    }
}

// -------- launch --------
extern "C" void kernel_launch(void* const* d_in, const int* in_sizes, int n_in,
                              void* d_out, int out_size) {
    const float* feat = nullptr;
    const float* mask = nullptr;
    const float* W    = nullptr;
    const float* bias = nullptr;
    const float* pi   = nullptr;
    for (int i = 0; i < n_in; i++) {
        switch (in_sizes[i]) {
            case BB * NF: feat = (const float*)d_in[i]; break;
            case NU * NF: mask = (const float*)d_in[i]; break;
            case NU * NL: W    = (const float*)d_in[i]; break;
            case NL:      bias = (const float*)d_in[i]; break;
            case NL * NC: pi   = (const float*)d_in[i]; break;
            default: break;
        }
    }
    if (!feat && n_in > 0) feat = (const float*)d_in[0];
    if (!mask && n_in > 1) mask = (const float*)d_in[1];
    if (!W    && n_in > 2) W    = (const float*)d_in[2];
    if (!bias && n_in > 3) bias = (const float*)d_in[3];
    if (!pi   && n_in > 4) pi   = (const float*)d_in[4];

    k_idx<<<NU, 128>>>(mask);
    k_gather<<<BB / 4, 256>>>(feat);
    k_wconv<<<256, 256>>>(W);
    k_softmax<<<128, 256>>>(pi);
    k_gemm1<<<dim3(NL / 128, BB / 128), 256>>>(bias);
    k_mu<<<BB / 16, 256>>>();
    k_gemm2<<<BB / 64, 256>>>((float*)d_out);
    (void)out_size;
}

// round 4
// speedup vs baseline: 1.6703x; 1.1311x over previous
#include <cuda_runtime.h>
#include <cuda_bf16.h>
#include <mma.h>
#include <cstdint>
#include <cstddef>

using namespace nvcuda;

#define BB 16384   // batch
#define NF 512     // features
#define NU 256     // used features
#define NL 1024    // leaves / decision node slots
#define NC 100     // classes
#define NCP 128    // classes padded

// -------- device scratch (static; no allocations anywhere) --------
__device__ int            g_idx[NU];
__device__ __nv_bfloat16  g_xb[(size_t)BB * NU];
__device__ __nv_bfloat16  g_Wb[(size_t)NU * NL];
__device__ __nv_bfloat16  g_probs[(size_t)NL * NCP];
__device__ __nv_bfloat16  g_d[(size_t)BB * NL];

// -------- cp.async helpers --------
__device__ __forceinline__ void cpa16(void* smem, const void* gmem) {
    uint32_t s = (uint32_t)__cvta_generic_to_shared(smem);
    asm volatile("cp.async.cg.shared.global [%0], [%1], 16;\n" :: "r"(s), "l"(gmem));
}
__device__ __forceinline__ void cpa_commit() { asm volatile("cp.async.commit_group;\n" ::: "memory"); }
template<int N> __device__ __forceinline__ void cpa_wait() { asm volatile("cp.async.wait_group %0;\n" :: "n"(N) : "memory"); }

// -------- prep: one block per used-feature, find its one-hot column --------
__global__ void k_idx(const float* __restrict__ mask) {
    int j = blockIdx.x;                 // 256 blocks, 128 threads
    int t = threadIdx.x;
    float4 v = reinterpret_cast<const float4*>(mask + (size_t)j * NF)[t];
    int f = -1;
    if      (v.x > 0.5f) f = 4 * t;
    else if (v.y > 0.5f) f = 4 * t + 1;
    else if (v.z > 0.5f) f = 4 * t + 2;
    else if (v.w > 0.5f) f = 4 * t + 3;
    if (f >= 0) g_idx[j] = f;
}

// -------- coalesced gather: 4 rows/block via SMEM staging --------
__global__ __launch_bounds__(256) void k_gather(const float* __restrict__ feat) {
    __shared__ float rows[4][NF];
    __shared__ int sidx[NU];
    int t = threadIdx.x;
    sidx[t] = g_idx[t];
    int row0 = blockIdx.x * 4;
    const float4* src = reinterpret_cast<const float4*>(feat + (size_t)row0 * NF);
    float4* dst4 = reinterpret_cast<float4*>(&rows[0][0]);
    dst4[t] = src[t];
    dst4[t + 256] = src[t + 256];
    __syncthreads();
#pragma unroll
    for (int r = 0; r < 4; r++)
        g_xb[(size_t)(row0 + r) * NU + t] = __float2bfloat16(rows[r][sidx[t]]);
}

// -------- merged prep: blocks 0..255 = W f32->bf16, blocks 256..383 = softmax(pi) --------
__global__ __launch_bounds__(256) void k_prep(const float* __restrict__ W,
                                              const float* __restrict__ pi) {
    int b = blockIdx.x;
    if (b < 256) {
        int i = b * 256 + threadIdx.x;      // 65536 threads, float4 each
        float4 v = reinterpret_cast<const float4*>(W)[i];
        __nv_bfloat162 p0 = __floats2bfloat162_rn(v.x, v.y);
        __nv_bfloat162 p1 = __floats2bfloat162_rn(v.z, v.w);
        uint2 u;
        u.x = *reinterpret_cast<unsigned*>(&p0);
        u.y = *reinterpret_cast<unsigned*>(&p1);
        reinterpret_cast<uint2*>(g_Wb)[i] = u;
    } else {
        int w = (b - 256) * 8 + (threadIdx.x >> 5);   // 128 blocks x 8 warps = 1024 rows
        int lane = threadIdx.x & 31;
        const float* row = pi + (size_t)w * NC;
        float4 v;
        if (lane < 25) v = reinterpret_cast<const float4*>(row)[lane];
        else v = make_float4(-1e30f, -1e30f, -1e30f, -1e30f);
        float m = fmaxf(fmaxf(v.x, v.y), fmaxf(v.z, v.w));
#pragma unroll
        for (int o = 16; o > 0; o >>= 1) m = fmaxf(m, __shfl_xor_sync(0xffffffffu, m, o));
        float e0 = (lane < 25) ? expf(v.x - m) : 0.f;
        float e1 = (lane < 25) ? expf(v.y - m) : 0.f;
        float e2 = (lane < 25) ? expf(v.z - m) : 0.f;
        float e3 = (lane < 25) ? expf(v.w - m) : 0.f;
        float s = e0 + e1 + e2 + e3;
#pragma unroll
        for (int o = 16; o > 0; o >>= 1) s += __shfl_xor_sync(0xffffffffu, s, o);
        float inv = 1.f / s;
        __nv_bfloat162 p0 = __floats2bfloat162_rn(e0 * inv, e1 * inv);
        __nv_bfloat162 p1 = __floats2bfloat162_rn(e2 * inv, e3 * inv);
        uint2 u;
        u.x = *reinterpret_cast<unsigned*>(&p0);
        u.y = *reinterpret_cast<unsigned*>(&p1);
        reinterpret_cast<uint2*>(g_probs + (size_t)w * NCP)[lane] = u;
    }
}

// -------- GEMM1: d = sigmoid(xb @ Wb + b)  [16384x1024x256]
// 128x128 tile, BK=64, 2-stage cp.async, dynamic smem 71680 B.
#define G1_AS 72    // A smem stride (bf16 elems)
#define G1_BS 136   // B smem stride
#define G1_A_BYTES (128 * G1_AS * 2)   // 18432
#define G1_B_BYTES (64 * G1_BS * 2)    // 17408
__global__ __launch_bounds__(256) void k_gemm1(const float* __restrict__ bias) {
    extern __shared__ __align__(16) unsigned char smem[];
    __nv_bfloat16* As = reinterpret_cast<__nv_bfloat16*>(smem);                     // 2 x 128x72
    __nv_bfloat16* Bs = reinterpret_cast<__nv_bfloat16*>(smem + 2 * G1_A_BYTES);    // 2 x 64x136
    float*         Cs = reinterpret_cast<float*>(smem);                             // 64x132 (reuse)

    int tid = threadIdx.x, wid = tid >> 5;
    int wm = wid & 3, wn = wid >> 2;           // 4(m) x 2(n), warp tile 32x64
    int row0 = blockIdx.y * 128, n0 = blockIdx.x * 128;

    wmma::fragment<wmma::accumulator, 16, 16, 16, float> acc[2][4];
#pragma unroll
    for (int i = 0; i < 2; i++)
#pragma unroll
        for (int j = 0; j < 4; j++) wmma::fill_fragment(acc[i][j], 0.f);

    auto load_stage = [&](int st, int ko) {
        __nv_bfloat16* a = As + st * 128 * G1_AS;
        __nv_bfloat16* b = Bs + st * 64 * G1_BS;
        // A: 128 rows x 64 cols = 1024 uint4, 4/thread
#pragma unroll
        for (int s = tid; s < 1024; s += 256) {
            int r = s >> 3, c = (s & 7) * 8;
            cpa16(a + r * G1_AS + c, g_xb + (size_t)(row0 + r) * NU + ko + c);
        }
        // B: 64 rows x 128 cols = 1024 uint4, 4/thread
#pragma unroll
        for (int s = tid; s < 1024; s += 256) {
            int r = s >> 4, c = (s & 15) * 8;
            cpa16(b + r * G1_BS + c, g_Wb + (size_t)(ko + r) * NL + n0 + c);
        }
        cpa_commit();
    };

    load_stage(0, 0);
    const int NCH = NU / 64;   // 4
    for (int ch = 0; ch < NCH; ch++) {
        if (ch + 1 < NCH) { load_stage((ch + 1) & 1, (ch + 1) * 64); cpa_wait<1>(); }
        else              { cpa_wait<0>(); }
        __syncthreads();
        const __nv_bfloat16* a = As + (ch & 1) * 128 * G1_AS;
        const __nv_bfloat16* b = Bs + (ch & 1) * 64 * G1_BS;
#pragma unroll
        for (int kk = 0; kk < 4; kk++) {
            wmma::fragment<wmma::matrix_a, 16, 16, 16, __nv_bfloat16, wmma::row_major> af[2];
            wmma::fragment<wmma::matrix_b, 16, 16, 16, __nv_bfloat16, wmma::row_major> bf[4];
#pragma unroll
            for (int i = 0; i < 2; i++)
                wmma::load_matrix_sync(af[i], a + (wm * 32 + i * 16) * G1_AS + kk * 16, G1_AS);
#pragma unroll
            for (int j = 0; j < 4; j++)
                wmma::load_matrix_sync(bf[j], b + (kk * 16) * G1_BS + wn * 64 + j * 16, G1_BS);
#pragma unroll
            for (int i = 0; i < 2; i++)
#pragma unroll
                for (int j = 0; j < 4; j++)
                    wmma::mma_sync(acc[i][j], af[i], bf[j], acc[i][j]);
        }
        __syncthreads();
    }

    // epilogue: two 64-row halves through SMEM, bias + sigmoid, bf16 store
    for (int h = 0; h < 2; h++) {
        if ((wm >> 1) == h) {
#pragma unroll
            for (int i = 0; i < 2; i++)
#pragma unroll
                for (int j = 0; j < 4; j++)
                    wmma::store_matrix_sync(Cs + ((wm & 1) * 32 + i * 16) * 132 + wn * 64 + j * 16,
                                            acc[i][j], 132, wmma::mem_row_major);
        }
        __syncthreads();
#pragma unroll
        for (int s = tid; s < 64 * 128; s += 256) {
            int r = s >> 7, c = s & 127;
            float z = Cs[r * 132 + c] + bias[n0 + c];
            float dv = 1.f / (1.f + __expf(-z));
            g_d[(size_t)(row0 + h * 64 + r) * NL + n0 + c] = __float2bfloat16(dv);
        }
        __syncthreads();
    }
}

// -------- fused tree-product + GEMM2: out = mu(d) @ probs  [16384x128x1024]
// 64-row block. d[64x1024] bf16 in SMEM; mu computed on the fly per 32-leaf K-chunk
// into double-buffered A staging; wmma 2(m)x4(n) warps, warp tile 32x32.
#define F2_DS 1032                       // d smem row stride (bf16)
#define F2_D_BYTES (64 * F2_DS * 2)      // 132096
#define F2_BS 136
#define F2_B_BYTES (32 * F2_BS * 2)      // 8704 per stage
#define F2_AS 40
#define F2_A_BYTES (64 * F2_AS * 2)      // 5120 per stage
#define F2_SMEM (F2_D_BYTES + 2 * F2_B_BYTES + 2 * F2_A_BYTES)   // 159744
__global__ __launch_bounds__(256) void k_fused2(float* __restrict__ out) {
    extern __shared__ __align__(16) unsigned char smem[];
    __nv_bfloat16* dsm = reinterpret_cast<__nv_bfloat16*>(smem);                         // 64 x 1032
    __nv_bfloat16* Bs  = reinterpret_cast<__nv_bfloat16*>(smem + F2_D_BYTES);            // 2 x 32x136
    __nv_bfloat16* As  = reinterpret_cast<__nv_bfloat16*>(smem + F2_D_BYTES + 2 * F2_B_BYTES); // 2 x 64x40
    float*         Cs  = reinterpret_cast<float*>(smem);                                 // reuse d region

    int tid = threadIdx.x, wid = tid >> 5;
    int wm = wid & 1, wn = wid >> 1;      // 2(m) x 4(n)
    int row0 = blockIdx.x * 64;

    // mu-compute mapping: thread u -> row = u>>2 (0..63), grp = u&3 (8 leaves each)
    int mrow = tid >> 2, mgrp = tid & 3;
    const __nv_bfloat16* drow = dsm + mrow * F2_DS;

    wmma::fragment<wmma::accumulator, 16, 16, 16, float> acc[2][2];
#pragma unroll
    for (int i = 0; i < 2; i++)
#pragma unroll
        for (int j = 0; j < 2; j++) wmma::fill_fragment(acc[i][j], 0.f);

    auto load_B = [&](int st, int ko) {
        __nv_bfloat16* b = Bs + st * 32 * F2_BS;
#pragma unroll
        for (int s = tid; s < 512; s += 256) {
            int r = s >> 4, c = (s & 15) * 8;
            cpa16(b + r * F2_BS + c, g_probs + (size_t)(ko + r) * NCP + c);
        }
        cpa_commit();
    };

    // compute mu for 32-leaf chunk ch into A stage st
    auto make_mu = [&](int st, int ch) {
        int h = ch * 4 + mgrp;            // leaf-group index = l>>3, 0..127
        // prefix levels 0..6 (constant within the 8-leaf group)
        float P = 1.f;
#pragma unroll
        for (int lev = 0; lev < 7; lev++) {
            int node = (1 << lev) + (h >> (7 - lev));
            int bit  = (h >> (6 - lev)) & 1;
            float dv = __bfloat162float(drow[node]);
            P *= bit ? (1.f - dv) : dv;
        }
        float d7 = __bfloat162float(drow[128 + h]);
        __nv_bfloat162 p8 = *reinterpret_cast<const __nv_bfloat162*>(drow + 256 + 2 * h);
        float d8a = __bfloat162float(__low2bfloat16(p8));
        float d8b = __bfloat162float(__high2bfloat16(p8));
        uint2 q9 = *reinterpret_cast<const uint2*>(drow + 512 + 4 * h);
        __nv_bfloat162 q9a = *reinterpret_cast<__nv_bfloat162*>(&q9.x);
        __nv_bfloat162 q9b = *reinterpret_cast<__nv_bfloat162*>(&q9.y);
        float d90 = __bfloat162float(__low2bfloat16(q9a));
        float d91 = __bfloat162float(__high2bfloat16(q9a));
        float d92 = __bfloat162float(__low2bfloat16(q9b));
        float d93 = __bfloat162float(__high2bfloat16(q9b));
        float pa = P * d7;
        float pb = P * (1.f - d7);
        float m0 = pa * d8a * d90;
        float m1 = pa * d8a * (1.f - d90);
        float m2 = pa * (1.f - d8a) * d91;
        float m3 = pa * (1.f - d8a) * (1.f - d91);
        float m4 = pb * d8b * d92;
        float m5 = pb * d8b * (1.f - d92);
        float m6 = pb * (1.f - d8b) * d93;
        float m7 = pb * (1.f - d8b) * (1.f - d93);
        __nv_bfloat162 o0 = __floats2bfloat162_rn(m0, m1);
        __nv_bfloat162 o1 = __floats2bfloat162_rn(m2, m3);
        __nv_bfloat162 o2 = __floats2bfloat162_rn(m4, m5);
        __nv_bfloat162 o3 = __floats2bfloat162_rn(m6, m7);
        uint4 u;
        u.x = *reinterpret_cast<unsigned*>(&o0);
        u.y = *reinterpret_cast<unsigned*>(&o1);
        u.z = *reinterpret_cast<unsigned*>(&o2);
        u.w = *reinterpret_cast<unsigned*>(&o3);
        *reinterpret_cast<uint4*>(As + st * 64 * F2_AS + mrow * F2_AS + mgrp * 8) = u;
    };

    // preload: d tile (group) then B chunk 0 (group)
#pragma unroll
    for (int s = tid; s < 8192; s += 256) {    // 64 rows x 128 uint4
        int r = s >> 7, c = (s & 127) * 8;
        cpa16(dsm + r * F2_DS + c, g_d + (size_t)(row0 + r) * NL + c);
    }
    cpa_commit();
    load_B(0, 0);
    cpa_wait<0>();
    __syncthreads();
    make_mu(0, 0);

    const int NCH = NL / 32;   // 32
    for (int ch = 0; ch < NCH; ch++) {
        if (ch + 1 < NCH) {
            load_B((ch + 1) & 1, (ch + 1) * 32);
            make_mu((ch + 1) & 1, ch + 1);
            cpa_wait<1>();
        } else {
            cpa_wait<0>();
        }
        __syncthreads();   // Bs[ch] ready; As[ch] writes visible
        const __nv_bfloat16* a = As + (ch & 1) * 64 * F2_AS;
        const __nv_bfloat16* b = Bs + (ch & 1) * 32 * F2_BS;
#pragma unroll
        for (int kk = 0; kk < 2; kk++) {
            wmma::fragment<wmma::matrix_a, 16, 16, 16, __nv_bfloat16, wmma::row_major> af[2];
            wmma::fragment<wmma::matrix_b, 16, 16, 16, __nv_bfloat16, wmma::row_major> bf[2];
#pragma unroll
            for (int i = 0; i < 2; i++)
                wmma::load_matrix_sync(af[i], a + (wm * 32 + i * 16) * F2_AS + kk * 16, F2_AS);
#pragma unroll
            for (int j = 0; j < 2; j++)
                wmma::load_matrix_sync(bf[j], b + (kk * 16) * F2_BS + wn * 32 + j * 16, F2_BS);
#pragma unroll
            for (int i = 0; i < 2; i++)
#pragma unroll
                for (int j = 0; j < 2; j++)
                    wmma::mma_sync(acc[i][j], af[i], bf[j], acc[i][j]);
        }
        __syncthreads();   // mma done before As/Bs stage reuse next iter
    }

    // epilogue: 64x128 into Cs (reuses d region; d no longer needed), write cols < 100
#pragma unroll
    for (int i = 0; i < 2; i++)
#pragma unroll
        for (int j = 0; j < 2; j++)
            wmma::store_matrix_sync(Cs + (wm * 32 + i * 16) * 132 + wn * 32 + j * 16,
                                    acc[i][j], 132, wmma::mem_row_major);
    __syncthreads();
#pragma unroll
    for (int s = tid; s < 64 * 128; s += 256) {
        int r = s >> 7, c = s & 127;
        if (c < NC)
            out[(size_t)(row0 + r) * NC + c] = Cs[r * 132 + c];
    }
}

// -------- launch --------
extern "C" void kernel_launch(void* const* d_in, const int* in_sizes, int n_in,
                              void* d_out, int out_size) {
    const float* feat = nullptr;
    const float* mask = nullptr;
    const float* W    = nullptr;
    const float* bias = nullptr;
    const float* pi   = nullptr;
    for (int i = 0; i < n_in; i++) {
        switch (in_sizes[i]) {
            case BB * NF: feat = (const float*)d_in[i]; break;
            case NU * NF: mask = (const float*)d_in[i]; break;
            case NU * NL: W    = (const float*)d_in[i]; break;
            case NL:      bias = (const float*)d_in[i]; break;
            case NL * NC: pi   = (const float*)d_in[i]; break;
            default: break;
        }
    }
    if (!feat && n_in > 0) feat = (const float*)d_in[0];
    if (!mask && n_in > 1) mask = (const float*)d_in[1];
    if (!W    && n_in > 2) W    = (const float*)d_in[2];
    if (!bias && n_in > 3) bias = (const float*)d_in[3];
    if (!pi   && n_in > 4) pi   = (const float*)d_in[4];

    cudaFuncSetAttribute(k_gemm1,  cudaFuncAttributeMaxDynamicSharedMemorySize,
                         2 * G1_A_BYTES + 2 * G1_B_BYTES);
    cudaFuncSetAttribute(k_fused2, cudaFuncAttributeMaxDynamicSharedMemorySize, F2_SMEM);

    k_idx<<<NU, 128>>>(mask);
    k_gather<<<BB / 4, 256>>>(feat);
    k_prep<<<384, 256>>>(W, pi);
    k_gemm1<<<dim3(NL / 128, BB / 128), 256, 2 * G1_A_BYTES + 2 * G1_B_BYTES>>>(bias);
    k_fused2<<<BB / 64, 256, F2_SMEM>>>((float*)d_out);
    (void)out_size;
}